// round 3
// baseline (speedup 1.0000x reference)
#include <cuda_runtime.h>
#include <math.h>

#define NMAX 1000000

// Scratch (device globals — no allocation allowed in kernel_launch)
__device__ float  g_deg [NMAX];
__device__ float  g_dinv[NMAX];
__device__ float4 g_g1  [NMAX];
__device__ float4 g_acc1[NMAX];
__device__ float4 g_g2  [NMAX];
__device__ float4 g_acc2[NMAX];

__device__ __forceinline__ void red_add_v4(float4* addr, float4 v) {
    asm volatile("red.global.add.v4.f32 [%0], {%1,%2,%3,%4};"
                 :: "l"(addr), "f"(v.x), "f"(v.y), "f"(v.z), "f"(v.w)
                 : "memory");
}

// deg init = 1.0 (self loop)
__global__ void k_init(int n) {
    int i = blockIdx.x * blockDim.x + threadIdx.x;
    if (i < n) g_deg[i] = 1.0f;
}

// deg[dst] += 1 over all edges (4 edges/thread, int4 loads)
__global__ void k_degree(const int* __restrict__ dst, int e) {
    int i = blockIdx.x * blockDim.x + threadIdx.x;
    int base = i * 4;
    if (base + 3 < e) {
        int4 d = *reinterpret_cast<const int4*>(dst + base);
        atomicAdd(&g_deg[d.x], 1.0f);
        atomicAdd(&g_deg[d.y], 1.0f);
        atomicAdd(&g_deg[d.z], 1.0f);
        atomicAdd(&g_deg[d.w], 1.0f);
    } else {
        for (int j = base; j < e; ++j) atomicAdd(&g_deg[dst[j]], 1.0f);
    }
}

// dinv = rsqrt(deg); g1 = (x @ W1) * dinv; acc1 = g1 (self-loop init)
__global__ void k_xform1(const float* __restrict__ x,
                         const float* __restrict__ W1, int n) {
    int i = blockIdx.x * blockDim.x + threadIdx.x;
    if (i >= n) return;
    float2 xi = reinterpret_cast<const float2*>(x)[i];
    float di = rsqrtf(g_deg[i]);
    g_dinv[i] = di;
    float4 h;
    h.x = (xi.x * W1[0] + xi.y * W1[4]) * di;
    h.y = (xi.x * W1[1] + xi.y * W1[5]) * di;
    h.z = (xi.x * W1[2] + xi.y * W1[6]) * di;
    h.w = (xi.x * W1[3] + xi.y * W1[7]) * di;
    g_g1[i] = h;
    g_acc1[i] = h;
}

// acc1[dst] += g1[src]  (vector red, 4 edges/thread)
__global__ void k_scatter1(const int* __restrict__ src,
                           const int* __restrict__ dst, int e) {
    int i = blockIdx.x * blockDim.x + threadIdx.x;
    int base = i * 4;
    if (base + 3 < e) {
        int4 s = *reinterpret_cast<const int4*>(src + base);
        int4 d = *reinterpret_cast<const int4*>(dst + base);
        float4 v0 = g_g1[s.x];
        float4 v1 = g_g1[s.y];
        float4 v2 = g_g1[s.z];
        float4 v3 = g_g1[s.w];
        red_add_v4(&g_acc1[d.x], v0);
        red_add_v4(&g_acc1[d.y], v1);
        red_add_v4(&g_acc1[d.z], v2);
        red_add_v4(&g_acc1[d.w], v3);
    } else {
        for (int j = base; j < e; ++j)
            red_add_v4(&g_acc1[dst[j]], g_g1[src[j]]);
    }
}

// h1 = relu(acc1*dinv + b1); g2 = (h1 @ W2) * dinv (padded to float4); acc2 = g2
__global__ void k_xform2(const float* __restrict__ W2,
                         const float* __restrict__ b1, int n) {
    int i = blockIdx.x * blockDim.x + threadIdx.x;
    if (i >= n) return;
    float di = g_dinv[i];
    float4 a = g_acc1[i];
    float h0 = fmaxf(a.x * di + b1[0], 0.0f);
    float h1 = fmaxf(a.y * di + b1[1], 0.0f);
    float h2 = fmaxf(a.z * di + b1[2], 0.0f);
    float h3 = fmaxf(a.w * di + b1[3], 0.0f);
    float4 g;
    g.x = (h0 * W2[0] + h1 * W2[3] + h2 * W2[6] + h3 * W2[9])  * di;
    g.y = (h0 * W2[1] + h1 * W2[4] + h2 * W2[7] + h3 * W2[10]) * di;
    g.z = (h0 * W2[2] + h1 * W2[5] + h2 * W2[8] + h3 * W2[11]) * di;
    g.w = 0.0f;
    g_g2[i] = g;
    g_acc2[i] = g;
}

// acc2[dst] += g2[src]
__global__ void k_scatter2(const int* __restrict__ src,
                           const int* __restrict__ dst, int e) {
    int i = blockIdx.x * blockDim.x + threadIdx.x;
    int base = i * 4;
    if (base + 3 < e) {
        int4 s = *reinterpret_cast<const int4*>(src + base);
        int4 d = *reinterpret_cast<const int4*>(dst + base);
        float4 v0 = g_g2[s.x];
        float4 v1 = g_g2[s.y];
        float4 v2 = g_g2[s.z];
        float4 v3 = g_g2[s.w];
        red_add_v4(&g_acc2[d.x], v0);
        red_add_v4(&g_acc2[d.y], v1);
        red_add_v4(&g_acc2[d.z], v2);
        red_add_v4(&g_acc2[d.w], v3);
    } else {
        for (int j = base; j < e; ++j)
            red_add_v4(&g_acc2[dst[j]], g_g2[src[j]]);
    }
}

// h2 = sigmoid(acc2*dinv + b2); fused MLP head -> out
__global__ void k_final(const float* __restrict__ b2,
                        const float* __restrict__ W3, const float* __restrict__ b3,
                        const float* __restrict__ W4, const float* __restrict__ b4,
                        const float* __restrict__ W5, const float* __restrict__ b5,
                        float* __restrict__ out, int n) {
    int i = blockIdx.x * blockDim.x + threadIdx.x;
    if (i >= n) return;
    float di = g_dinv[i];
    float4 a = g_acc2[i];
    float h2_0 = 1.0f / (1.0f + expf(-(a.x * di + b2[0])));
    float h2_1 = 1.0f / (1.0f + expf(-(a.y * di + b2[1])));
    float h2_2 = 1.0f / (1.0f + expf(-(a.z * di + b2[2])));

    float h3[4];
#pragma unroll
    for (int j = 0; j < 4; ++j) {
        float t = h2_0 * W3[0 * 4 + j] + h2_1 * W3[1 * 4 + j] + h2_2 * W3[2 * 4 + j] + b3[j];
        h3[j] = fmaxf(t, 0.0f);
    }
    float h4[3];
#pragma unroll
    for (int k = 0; k < 3; ++k) {
        float t = h3[0] * W4[0 * 3 + k] + h3[1] * W4[1 * 3 + k] +
                  h3[2] * W4[2 * 3 + k] + h3[3] * W4[3 * 3 + k] + b4[k];
        h4[k] = fmaxf(t, 0.0f);
    }
    out[i] = h4[0] * W5[0] + h4[1] * W5[1] + h4[2] * W5[2] + b5[0];
}

extern "C" void kernel_launch(void* const* d_in, const int* in_sizes, int n_in,
                              void* d_out, int out_size) {
    const float* x  = (const float*)d_in[0];
    const int*   ei = (const int*)  d_in[1];
    const float* W1 = (const float*)d_in[2];
    const float* b1 = (const float*)d_in[3];
    const float* W2 = (const float*)d_in[4];
    const float* b2 = (const float*)d_in[5];
    const float* W3 = (const float*)d_in[6];
    const float* b3 = (const float*)d_in[7];
    const float* W4 = (const float*)d_in[8];
    const float* b4 = (const float*)d_in[9];
    const float* W5 = (const float*)d_in[10];
    const float* b5 = (const float*)d_in[11];

    int n = in_sizes[0] / 2;   // [N, 2] node features
    int e = in_sizes[1] / 2;   // [2, E] edge index
    const int* src = ei;
    const int* dst = ei + e;

    const int TB = 256;
    int nb  = (n + TB - 1) / TB;
    int et  = (e + 3) / 4;               // 4 edges per thread
    int eb  = (et + TB - 1) / TB;

    k_init    <<<nb, TB>>>(n);
    k_degree  <<<eb, TB>>>(dst, e);
    k_xform1  <<<nb, TB>>>(x, W1, n);
    k_scatter1<<<eb, TB>>>(src, dst, e);
    k_xform2  <<<nb, TB>>>(W2, b1, n);
    k_scatter2<<<eb, TB>>>(src, dst, e);
    k_final   <<<nb, TB>>>(b2, W3, b3, W4, b4, W5, b5, (float*)d_out, n);
}

// round 7
// speedup vs baseline: 1.0183x; 1.0183x over previous
#include <cuda_runtime.h>
#include <math.h>

#define NMAX 1000000

// Scratch (device globals — no allocation allowed in kernel_launch)
__device__ float  g_deg [NMAX];
__device__ float  g_dinv[NMAX];
__device__ float2 g_g1  [NMAX];   // x * dinv  (rank-2 payload, W1 applied post-aggregation)
__device__ float2 g_acc1[NMAX];
__device__ float4 g_g2  [NMAX];   // (h1 @ W2) * dinv, padded to 4
__device__ float4 g_acc2[NMAX];

__device__ __forceinline__ void red_add_v4(float4* addr, float4 v) {
    asm volatile("red.global.add.v4.f32 [%0], {%1,%2,%3,%4};"
                 :: "l"(addr), "f"(v.x), "f"(v.y), "f"(v.z), "f"(v.w)
                 : "memory");
}

__device__ __forceinline__ void red_add_v2(float2* addr, float2 v) {
    asm volatile("red.global.add.v2.f32 [%0], {%1,%2};"
                 :: "l"(addr), "f"(v.x), "f"(v.y)
                 : "memory");
}

// deg init = 1.0 (self loop)
__global__ void __launch_bounds__(256) k_init(int n) {
    int i = blockIdx.x * blockDim.x + threadIdx.x;
    if (i < n) g_deg[i] = 1.0f;
}

// deg[dst] += 1 over all edges (4 edges/thread, int4 loads)
__global__ void __launch_bounds__(256) k_degree(const int* __restrict__ dst, int e) {
    int i = blockIdx.x * blockDim.x + threadIdx.x;
    int base = i * 4;
    if (base + 3 < e) {
        int4 d = *reinterpret_cast<const int4*>(dst + base);
        atomicAdd(&g_deg[d.x], 1.0f);
        atomicAdd(&g_deg[d.y], 1.0f);
        atomicAdd(&g_deg[d.z], 1.0f);
        atomicAdd(&g_deg[d.w], 1.0f);
    } else {
        for (int j = base; j < e; ++j) atomicAdd(&g_deg[dst[j]], 1.0f);
    }
}

// dinv = rsqrt(deg); g1 = x * dinv (2 floats); acc1 = g1 (self-loop init)
__global__ void __launch_bounds__(256) k_xform1(const float* __restrict__ x, int n) {
    int i = blockIdx.x * blockDim.x + threadIdx.x;
    if (i >= n) return;
    float2 xi = reinterpret_cast<const float2*>(x)[i];
    float di = rsqrtf(g_deg[i]);
    g_dinv[i] = di;
    float2 g;
    g.x = xi.x * di;
    g.y = xi.y * di;
    g_g1[i]   = g;
    g_acc1[i] = g;
}

// acc1[dst] += g1[src]  (vector red v2, 4 edges/thread)
__global__ void __launch_bounds__(256) k_scatter1(const int* __restrict__ src,
                                                  const int* __restrict__ dst, int e) {
    int i = blockIdx.x * blockDim.x + threadIdx.x;
    int base = i * 4;
    if (base + 3 < e) {
        int4 s = *reinterpret_cast<const int4*>(src + base);
        int4 d = *reinterpret_cast<const int4*>(dst + base);
        float2 v0 = g_g1[s.x];
        float2 v1 = g_g1[s.y];
        float2 v2 = g_g1[s.z];
        float2 v3 = g_g1[s.w];
        red_add_v2(&g_acc1[d.x], v0);
        red_add_v2(&g_acc1[d.y], v1);
        red_add_v2(&g_acc1[d.z], v2);
        red_add_v2(&g_acc1[d.w], v3);
    } else {
        for (int j = base; j < e; ++j)
            red_add_v2(&g_acc1[dst[j]], g_g1[src[j]]);
    }
}

// z1 = (acc1*dinv) @ W1 + b1 ; h1 = relu(z1) ; g2 = (h1 @ W2) * dinv ; acc2 = g2
__global__ void __launch_bounds__(256) k_xform2(const float* __restrict__ W1,
                                                const float* __restrict__ b1,
                                                const float* __restrict__ W2, int n) {
    int i = blockIdx.x * blockDim.x + threadIdx.x;
    if (i >= n) return;
    float di = g_dinv[i];
    float2 a = g_acc1[i];
    float ax = a.x * di, ay = a.y * di;
    float h0 = fmaxf(ax * W1[0] + ay * W1[4] + b1[0], 0.0f);
    float h1 = fmaxf(ax * W1[1] + ay * W1[5] + b1[1], 0.0f);
    float h2 = fmaxf(ax * W1[2] + ay * W1[6] + b1[2], 0.0f);
    float h3 = fmaxf(ax * W1[3] + ay * W1[7] + b1[3], 0.0f);
    float4 g;
    g.x = (h0 * W2[0] + h1 * W2[3] + h2 * W2[6] + h3 * W2[9])  * di;
    g.y = (h0 * W2[1] + h1 * W2[4] + h2 * W2[7] + h3 * W2[10]) * di;
    g.z = (h0 * W2[2] + h1 * W2[5] + h2 * W2[8] + h3 * W2[11]) * di;
    g.w = 0.0f;
    g_g2[i]   = g;
    g_acc2[i] = g;
}

// acc2[dst] += g2[src]
__global__ void __launch_bounds__(256) k_scatter2(const int* __restrict__ src,
                                                  const int* __restrict__ dst, int e) {
    int i = blockIdx.x * blockDim.x + threadIdx.x;
    int base = i * 4;
    if (base + 3 < e) {
        int4 s = *reinterpret_cast<const int4*>(src + base);
        int4 d = *reinterpret_cast<const int4*>(dst + base);
        float4 v0 = g_g2[s.x];
        float4 v1 = g_g2[s.y];
        float4 v2 = g_g2[s.z];
        float4 v3 = g_g2[s.w];
        red_add_v4(&g_acc2[d.x], v0);
        red_add_v4(&g_acc2[d.y], v1);
        red_add_v4(&g_acc2[d.z], v2);
        red_add_v4(&g_acc2[d.w], v3);
    } else {
        for (int j = base; j < e; ++j)
            red_add_v4(&g_acc2[dst[j]], g_g2[src[j]]);
    }
}

// h2 = sigmoid(acc2*dinv + b2); fused MLP head -> out
__global__ void __launch_bounds__(256) k_final(const float* __restrict__ b2,
                        const float* __restrict__ W3, const float* __restrict__ b3,
                        const float* __restrict__ W4, const float* __restrict__ b4,
                        const float* __restrict__ W5, const float* __restrict__ b5,
                        float* __restrict__ out, int n) {
    int i = blockIdx.x * blockDim.x + threadIdx.x;
    if (i >= n) return;
    float di = g_dinv[i];
    float4 a = g_acc2[i];
    float h2_0 = 1.0f / (1.0f + expf(-(a.x * di + b2[0])));
    float h2_1 = 1.0f / (1.0f + expf(-(a.y * di + b2[1])));
    float h2_2 = 1.0f / (1.0f + expf(-(a.z * di + b2[2])));

    float h3[4];
#pragma unroll
    for (int j = 0; j < 4; ++j) {
        float t = h2_0 * W3[0 * 4 + j] + h2_1 * W3[1 * 4 + j] + h2_2 * W3[2 * 4 + j] + b3[j];
        h3[j] = fmaxf(t, 0.0f);
    }
    float h4[3];
#pragma unroll
    for (int k = 0; k < 3; ++k) {
        float t = h3[0] * W4[0 * 3 + k] + h3[1] * W4[1 * 3 + k] +
                  h3[2] * W4[2 * 3 + k] + h3[3] * W4[3 * 3 + k] + b4[k];
        h4[k] = fmaxf(t, 0.0f);
    }
    out[i] = h4[0] * W5[0] + h4[1] * W5[1] + h4[2] * W5[2] + b5[0];
}

extern "C" void kernel_launch(void* const* d_in, const int* in_sizes, int n_in,
                              void* d_out, int out_size) {
    const float* x  = (const float*)d_in[0];
    const int*   ei = (const int*)  d_in[1];
    const float* W1 = (const float*)d_in[2];
    const float* b1 = (const float*)d_in[3];
    const float* W2 = (const float*)d_in[4];
    const float* b2 = (const float*)d_in[5];
    const float* W3 = (const float*)d_in[6];
    const float* b3 = (const float*)d_in[7];
    const float* W4 = (const float*)d_in[8];
    const float* b4 = (const float*)d_in[9];
    const float* W5 = (const float*)d_in[10];
    const float* b5 = (const float*)d_in[11];

    int n = in_sizes[0] / 2;   // [N, 2] node features
    int e = in_sizes[1] / 2;   // [2, E] edge index
    const int* src = ei;
    const int* dst = ei + e;

    const int TB = 256;
    int nb  = (n + TB - 1) / TB;
    int et  = (e + 3) / 4;               // 4 edges per thread
    int eb  = (et + TB - 1) / TB;

    k_init    <<<nb, TB>>>(n);
    k_degree  <<<eb, TB>>>(dst, e);
    k_xform1  <<<nb, TB>>>(x, n);
    k_scatter1<<<eb, TB>>>(src, dst, e);
    k_xform2  <<<nb, TB>>>(W1, b1, W2, n);
    k_scatter2<<<eb, TB>>>(src, dst, e);
    k_final   <<<nb, TB>>>(b2, W3, b3, W4, b4, W5, b5, (float*)d_out, n);
}